// round 11
// baseline (speedup 1.0000x reference)
#include <cuda_runtime.h>
#include <cstdint>

#define B_   256
#define T_   512
#define DIN  128
#define H_   512
#define DOUT 64
#define KB   8       // k-rows per register block
#define NBLK 16      // blocks per k-quarter (128 k)

// Scratch (allocation-free rule: __device__ globals)
__device__ float g_xproj[(size_t)B_ * T_ * H_];  // [b][t][h] = inputs@Win + brec
__device__ float g_hall [(size_t)B_ * T_ * H_];  // [b][t][h] = h_t for all t

// Packed fp32x2 FMA
union F2U { float2 f; unsigned long long u; };
__device__ __forceinline__ float2 ffma2(float2 a, float2 b, float2 c) {
    F2U A, Bv, C, D;
    A.f = a; Bv.f = b; C.f = c;
    asm("fma.rn.f32x2 %0, %1, %2, %3;" : "=l"(D.u) : "l"(A.u), "l"(Bv.u), "l"(C.u));
    return D.f;
}

// ---------------------------------------------------------------------------
// Kernel A: xproj = inputs @ Win + brec   (measured 584us)
// ---------------------------------------------------------------------------
__global__ void __launch_bounds__(256) rnn_xproj(
    const float* __restrict__ inputs,
    const float* __restrict__ Win,
    const float* __restrict__ brec)
{
    __shared__ __align__(16) float2 x_dup[16][DIN];
    const int tid = threadIdx.x;
    const size_t r0 = (size_t)blockIdx.x * 16;

    for (int i = tid; i < 16 * DIN; i += 256) {
        int r = i >> 7, k = i & (DIN - 1);
        float v = inputs[(r0 + r) * DIN + k];
        x_dup[r][k] = make_float2(v, v);
    }
    __syncthreads();

    const float2* __restrict__ W2 = reinterpret_cast<const float2*>(Win);
    float2 acc[16];
#pragma unroll
    for (int r = 0; r < 16; r++) acc[r] = make_float2(0.f, 0.f);

#pragma unroll 2
    for (int k = 0; k < DIN; k += 2) {
        float2 w0 = W2[(size_t)k * (H_ / 2) + tid];
        float2 w1 = W2[(size_t)(k + 1) * (H_ / 2) + tid];
#pragma unroll
        for (int r = 0; r < 16; r++) {
            float4 hx = *reinterpret_cast<const float4*>(&x_dup[r][k]);
            acc[r] = ffma2(make_float2(hx.x, hx.y), w0, acc[r]);
            acc[r] = ffma2(make_float2(hx.z, hx.w), w1, acc[r]);
        }
    }

    float2 bb = reinterpret_cast<const float2*>(brec)[tid];
    float2* __restrict__ out2 = reinterpret_cast<float2*>(g_xproj);
#pragma unroll
    for (int r = 0; r < 16; r++)
        out2[(r0 + r) * (H_ / 2) + tid] = make_float2(acc[r].x + bb.x, acc[r].y + bb.y);
}

// ---------------------------------------------------------------------------
// Kernel B: recurrence. 64 CTAs x 4 batch rows x 512 threads. Sync-free W
// streaming (LDG.128 double-buffered register blocks), 4-way k-split so 4
// warps/SMSP overlap the fma pipe with the L1tex W stream. Thread:
// p = tid>>7 (k-quarter; also the batch it finalizes), q = tid&127 -> cols
// 4q..4q+3. Step end: 4-way SMEM reduction (own partial kept in regs),
// tanh, h update. Exactly 2 __syncthreads per step; zero cross-CTA sync.
// ---------------------------------------------------------------------------
extern __shared__ __align__(16) unsigned char smraw[];

__global__ void __launch_bounds__(512, 1)
rnn_recurrent(const float* __restrict__ Wrec,
              const float* __restrict__ h0)
{
    float2* hdup = reinterpret_cast<float2*>(smraw);            // [2][4][512] {h,h} 32KB
    float4* red  = reinterpret_cast<float4*>(smraw + 32768);    // [4][4][128]       32KB

    const int tid = threadIdx.x;
    const int p   = tid >> 7;          // k-quarter 0..3 == batch finalized
    const int q   = tid & 127;         // col-quad
    const int c0  = 4 * q;
    const int k0  = 128 * p;
    const int b0  = blockIdx.x * 4;

    for (int i = tid; i < 4 * H_; i += 512) {   // h = h0 for all 4 rows (dup)
        int b = i >> 9, k = i & 511;
        float v = h0[k];
        hdup[(size_t)b * H_ + k] = make_float2(v, v);
    }
    __syncthreads();

    // W addresses as running byte offsets (minimal IMAD in the LDG chain).
    const char* wptr = reinterpret_cast<const char*>(Wrec + (size_t)k0 * H_ + c0);
    const size_t ROWB = H_ * 4;                    // 2KB per k-row
    float4 wb0[KB], wb1[KB];

#pragma unroll
    for (int kk = 0; kk < KB; kk++)                // prologue: block 0
        wb0[kk] = __ldg(reinterpret_cast<const float4*>(wptr + (size_t)kk * ROWB));

    float4 xp = *reinterpret_cast<const float4*>(
        g_xproj + ((size_t)(b0 + p) * T_) * H_ + c0);

    float2 acc[4][2];
#pragma unroll
    for (int b = 0; b < 4; b++) { acc[b][0] = make_float2(0.f,0.f); acc[b][1] = make_float2(0.f,0.f); }

    int hb = 0;
    for (int t = 0; t < T_; t++) {
        const float2* hbuf = hdup + (size_t)hb * 4 * H_;
#pragma unroll 1
        for (int bb = 0; bb < NBLK / 2; bb++) {
            const int blk0 = 2 * bb, blk1 = 2 * bb + 1;

            // prefetch blk1 -> wb1, compute blk0 from wb0
            {
                const char* pf = wptr + (size_t)blk1 * (KB * ROWB);
#pragma unroll
                for (int kk = 0; kk < KB; kk++)
                    wb1[kk] = __ldg(reinterpret_cast<const float4*>(pf + (size_t)kk * ROWB));
            }
            {
                const int kb = k0 + blk0 * KB;
#pragma unroll
                for (int kk = 0; kk < KB; kk += 2) {
                    float4 w0 = wb0[kk], w1 = wb0[kk + 1];
#pragma unroll
                    for (int b = 0; b < 4; b++) {
                        float4 hh = *reinterpret_cast<const float4*>(
                            &hbuf[(size_t)b * H_ + kb + kk]);
                        acc[b][0] = ffma2(make_float2(hh.x, hh.y), make_float2(w0.x, w0.y), acc[b][0]);
                        acc[b][1] = ffma2(make_float2(hh.x, hh.y), make_float2(w0.z, w0.w), acc[b][1]);
                        acc[b][0] = ffma2(make_float2(hh.z, hh.w), make_float2(w1.x, w1.y), acc[b][0]);
                        acc[b][1] = ffma2(make_float2(hh.z, hh.w), make_float2(w1.z, w1.w), acc[b][1]);
                    }
                }
            }

            // prefetch next-next block (wraps to 0 for next step) -> wb0, compute blk1
            {
                const int nblk = (blk1 + 1) & (NBLK - 1);
                const char* pf = wptr + (size_t)nblk * (KB * ROWB);
#pragma unroll
                for (int kk = 0; kk < KB; kk++)
                    wb0[kk] = __ldg(reinterpret_cast<const float4*>(pf + (size_t)kk * ROWB));
            }
            {
                const int kb = k0 + blk1 * KB;
#pragma unroll
                for (int kk = 0; kk < KB; kk += 2) {
                    float4 w0 = wb1[kk], w1 = wb1[kk + 1];
#pragma unroll
                    for (int b = 0; b < 4; b++) {
                        float4 hh = *reinterpret_cast<const float4*>(
                            &hbuf[(size_t)b * H_ + kb + kk]);
                        acc[b][0] = ffma2(make_float2(hh.x, hh.y), make_float2(w0.x, w0.y), acc[b][0]);
                        acc[b][1] = ffma2(make_float2(hh.x, hh.y), make_float2(w0.z, w0.w), acc[b][1]);
                        acc[b][0] = ffma2(make_float2(hh.z, hh.w), make_float2(w1.x, w1.y), acc[b][0]);
                        acc[b][1] = ffma2(make_float2(hh.z, hh.w), make_float2(w1.z, w1.w), acc[b][1]);
                    }
                }
            }
        }

        // ---- step end: 4-way cross-k reduction ----
        // red[b][p][q]: lane-consecutive in q -> conflict-free. Publish only
        // partials OTHER threads need; own batch-p partial stays in regs.
#pragma unroll
        for (int b = 0; b < 4; b++)
            if (b != p)
                red[((size_t)b * 4 + p) * 128 + q] =
                    make_float4(acc[b][0].x, acc[b][0].y, acc[b][1].x, acc[b][1].y);
        __syncthreads();

        float4 s = make_float4(acc[p][0].x, acc[p][0].y, acc[p][1].x, acc[p][1].y);
#pragma unroll
        for (int d = 1; d < 4; d++) {
            int pp = (p + d) & 3;                      // partner k-groups
            float4 r = red[((size_t)p * 4 + pp) * 128 + q];
            s.x += r.x; s.y += r.y; s.z += r.z; s.w += r.w;
        }
        float v0 = tanhf(s.x + xp.x);
        float v1 = tanhf(s.y + xp.y);
        float v2 = tanhf(s.z + xp.z);
        float v3 = tanhf(s.w + xp.w);

        *reinterpret_cast<float4*>(
            g_hall + ((size_t)(b0 + p) * T_ + t) * H_ + c0) = make_float4(v0, v1, v2, v3);

        float4* hdst = reinterpret_cast<float4*>(
            hdup + (size_t)(hb ^ 1) * 4 * H_ + (size_t)p * H_ + c0);
        hdst[0] = make_float4(v0, v0, v1, v1);
        hdst[1] = make_float4(v2, v2, v3, v3);

#pragma unroll
        for (int b = 0; b < 4; b++) { acc[b][0] = make_float2(0.f,0.f); acc[b][1] = make_float2(0.f,0.f); }
        if (t + 1 < T_)                               // hoisted: overlaps tail, not GEMM head
            xp = *reinterpret_cast<const float4*>(
                g_xproj + ((size_t)(b0 + p) * T_ + (t + 1)) * H_ + c0);
        __syncthreads();
        hb ^= 1;
    }
}

// ---------------------------------------------------------------------------
// Kernel C: out = g_hall @ Wout + bout
// ---------------------------------------------------------------------------
__global__ void __launch_bounds__(256, 1) rnn_outproj(
    const float* __restrict__ Wout,
    const float* __restrict__ bout,
    float* __restrict__ out)
{
    __shared__ __align__(16) float2 hdq[64][64];
    const int tid = threadIdx.x;
    const int pair = tid & 31;
    const int rg = tid >> 5;
    const size_t r0 = (size_t)blockIdx.x * 64;

    float2 acc[8];
#pragma unroll
    for (int i = 0; i < 8; i++) acc[i] = make_float2(0.f, 0.f);

    const float2* __restrict__ Wo2 = reinterpret_cast<const float2*>(Wout);

    for (int kc = 0; kc < H_; kc += 64) {
        __syncthreads();
        for (int i = tid; i < 64 * 64; i += 256) {
            int r = i >> 6, k = i & 63;
            float v = g_hall[(r0 + r) * H_ + kc + k];
            hdq[r][k] = make_float2(v, v);
        }
        __syncthreads();

#pragma unroll 4
        for (int kk = 0; kk < 64; kk += 2) {
            float2 w0 = Wo2[(size_t)(kc + kk) * (DOUT / 2) + pair];
            float2 w1 = Wo2[(size_t)(kc + kk + 1) * (DOUT / 2) + pair];
#pragma unroll
            for (int i = 0; i < 8; i++) {
                int r = rg * 8 + i;
                float4 hx = *reinterpret_cast<const float4*>(&hdq[r][kk]);
                acc[i] = ffma2(make_float2(hx.x, hx.y), w0, acc[i]);
                acc[i] = ffma2(make_float2(hx.z, hx.w), w1, acc[i]);
            }
        }
    }

    float2 bb = reinterpret_cast<const float2*>(bout)[pair];
    float2* __restrict__ out2 = reinterpret_cast<float2*>(out);
#pragma unroll
    for (int i = 0; i < 8; i++) {
        int r = rg * 8 + i;
        out2[(r0 + r) * (DOUT / 2) + pair] =
            make_float2(acc[i].x + bb.x, acc[i].y + bb.y);
    }
}

// ---------------------------------------------------------------------------
extern "C" void kernel_launch(void* const* d_in, const int* in_sizes, int n_in,
                              void* d_out, int out_size)
{
    const float* inputs = (const float*)d_in[0];
    const float* Win    = (const float*)d_in[1];
    const float* Wrec   = (const float*)d_in[2];
    const float* brec   = (const float*)d_in[3];
    const float* Wout   = (const float*)d_in[4];
    const float* bout   = (const float*)d_in[5];
    const float* h0     = (const float*)d_in[6];

    cudaFuncSetAttribute(rnn_recurrent,
                         cudaFuncAttributeMaxDynamicSharedMemorySize, 65536);

    rnn_xproj<<<(B_ * T_) / 16, 256>>>(inputs, Win, brec);
    rnn_recurrent<<<B_ / 4, 512, 65536>>>(Wrec, h0);
    rnn_outproj<<<(B_ * T_) / 64, 256>>>(Wout, bout, (float*)d_out);
}